// round 15
// baseline (speedup 1.0000x reference)
#include <cuda_runtime.h>
#include <cuda_fp16.h>
#include <cstdint>
#include <math_constants.h>

// ---------------------------------------------------------------------------
// Paged-cache block-diagonal causal attention (fill chunk), fused flash-attn.
// FP16 mma.sync m16n8k16 (fp32 accum), fp32 I/O.
// R15: R14 + warp-voted alpha-skip of the O rescale, STS.128 convert pass,
// tree max-reduction. cp.async staging pipeline, ctx smem prefetch, BM=128,
// direct S-accumulator -> PV A-fragment packing.
//
// kv j < 1792 -> cache[ctx32[s*2048+j]];  j >= 1792 -> new k/v row j-1792.
// Mask: kv j visible to query i iff j <= i + 1792.
// ---------------------------------------------------------------------------

namespace {
constexpr int kNSeqs   = 8;
constexpr int kQLen    = 256;
constexpr int kKvLen   = 2048;
constexpr int kHeads   = 16;
constexpr int kHeadDim = 128;
constexpr int kCtxOld  = 1792;
constexpr int kOutCols = 2048;

constexpr int BM = 128;
constexpr int BN = 64;
constexpr int kThreads = 256;  // 8 warps, 16 query rows each

constexpr float kScaleLog2e = 0.08838834764831845f * 1.4426950408889634f;

// u32 offsets. fp16 K/V tiles: 64 rows x 64 u32, XOR-swizzled
// (16B chunk index ^ (row & 7)). ctx slots: 1792 ints.
// fp32 staging: K,V 64 rows x 128 u32 each.
// Q prologue (128 rows x 64 u32) aliases the K+V tile regions exactly.
constexpr int kKOff   = 0;
constexpr int kVOff   = 4096;
constexpr int kCtxOff = 8192;
constexpr int kSKOff  = kCtxOff + kCtxOld;     // 9984
constexpr int kSVOff  = kSKOff + 64 * 128;     // 18176
constexpr int kSmemU32 = kSVOff + 64 * 128;    // 26368 u32 = 105472 B
}  // namespace

__device__ __forceinline__ uint32_t smem_u32(const void* p) {
    uint32_t a;
    asm("{ .reg .u64 t; cvta.to.shared.u64 t, %1; cvt.u32.u64 %0, t; }"
        : "=r"(a) : "l"(p));
    return a;
}

__device__ __forceinline__ uint32_t pack2(float lo, float hi) {
    __half2 h = __floats2half2_rn(lo, hi);
    return *reinterpret_cast<uint32_t*>(&h);
}

__device__ __forceinline__ float fast_exp2(float x) {
    float r;
    asm("ex2.approx.ftz.f32 %0, %1;" : "=f"(r) : "f"(x));
    return r;
}

__device__ __forceinline__ void mma_f16(float c[4], const uint32_t a[4],
                                        const uint32_t* b) {
    asm volatile(
        "mma.sync.aligned.m16n8k16.row.col.f32.f16.f16.f32 "
        "{%0,%1,%2,%3}, {%4,%5,%6,%7}, {%8,%9}, {%0,%1,%2,%3};"
        : "+f"(c[0]), "+f"(c[1]), "+f"(c[2]), "+f"(c[3])
        : "r"(a[0]), "r"(a[1]), "r"(a[2]), "r"(a[3]), "r"(b[0]), "r"(b[1]));
}

__device__ __forceinline__ void ldm_x4(uint32_t r[4], uint32_t addr) {
    asm volatile(
        "ldmatrix.sync.aligned.m8n8.x4.shared.b16 {%0,%1,%2,%3}, [%4];"
        : "=r"(r[0]), "=r"(r[1]), "=r"(r[2]), "=r"(r[3]) : "r"(addr));
}

__device__ __forceinline__ void ldm_x4_t(uint32_t r[4], uint32_t addr) {
    asm volatile(
        "ldmatrix.sync.aligned.m8n8.x4.trans.shared.b16 {%0,%1,%2,%3}, [%4];"
        : "=r"(r[0]), "=r"(r[1]), "=r"(r[2]), "=r"(r[3]) : "r"(addr));
}

#define CP_ASYNC16(dst, src) \
    asm volatile("cp.async.cg.shared.global [%0], [%1], 16;" \
                 :: "r"(dst), "l"(src) : "memory")
#define CP_COMMIT() asm volatile("cp.async.commit_group;" ::: "memory")
#define CP_WAIT0()  asm volatile("cp.async.wait_group 0;" ::: "memory")

__global__ void __launch_bounds__(kThreads, 1)
fa_fp16_kernel(const float* __restrict__ q, const float* __restrict__ kk,
               const float* __restrict__ vv, const float* __restrict__ k_cache,
               const float* __restrict__ v_cache,
               const int* __restrict__ ctx32, float* __restrict__ out) {
    extern __shared__ uint32_t smem[];
    const uint32_t sb = smem_u32(smem);

    const int qt = blockIdx.x;   // 0..1
    const int h  = blockIdx.y;   // 0..15
    const int s  = blockIdx.z;   // 0..7
    const int q0 = qt * BM;

    const int tid  = threadIdx.x;
    const int warp = tid >> 5;
    const int lane = tid & 31;
    const int g = lane >> 2;
    const int t = lane & 3;

    // ctx dtype probe (int64 LE -> odd words 1,3,5 all zero)
    const bool ctx_is64 =
        (ctx32[1] == 0) && (ctx32[3] == 0) && (ctx32[5] == 0);

    const int n_tiles = (q0 + BM - 1 + kCtxOld + 1 + BN - 1) / BN;  // 30 or 32

    const int rseg = lane >> 3;  // gather: row within group of 4
    const int c    = lane & 7;   // gather: 16B fp32 chunk within 128B pass

    // ---- issue cp.async gather of one tile into fp32 staging ----
    auto issue_gather = [&](int j0) {
#pragma unroll
        for (int rg = 0; rg < 2; rg++) {
            const int row = warp * 8 + rg * 4 + rseg;
            const int j = j0 + row;
            const float *ksrc, *vsrc;
            if (j < kCtxOld) {
                const int slot = (int)smem[kCtxOff + j];
                const size_t base = ((size_t)slot * kHeads + h) * kHeadDim;
                ksrc = k_cache + base;
                vsrc = v_cache + base;
            } else {
                const size_t base =
                    ((size_t)(s * kQLen + (j - kCtxOld)) * kHeads + h) * kHeadDim;
                ksrc = kk + base;
                vsrc = vv + base;
            }
#pragma unroll
            for (int pass = 0; pass < 4; pass++) {
                const uint32_t off =
                    (uint32_t)(row * 128 + pass * 32 + c * 4) * 4;
                CP_ASYNC16(sb + (uint32_t)kSKOff * 4 + off,
                           ksrc + pass * 32 + c * 4);
                CP_ASYNC16(sb + (uint32_t)kSVOff * 4 + off,
                           vsrc + pass * 32 + c * 4);
            }
        }
        CP_COMMIT();
    };

    // ---- convert fp32 staging -> swizzled fp16 tiles (STS.128) ----
    auto convert_tiles = [&]() {
#pragma unroll
        for (int it = 0; it < 4; it++) {
            const int chunk = tid + it * 256;   // 1024 16B-out chunks / tensor
            const int row = chunk >> 4;
            const int oc  = chunk & 15;
            const int col = ((oc ^ (row & 7)) << 2);
            float4 k0 = *(const float4*)(smem + kSKOff + row * 128 + oc * 8);
            float4 k1 = *(const float4*)(smem + kSKOff + row * 128 + oc * 8 + 4);
            uint4 ku;
            ku.x = pack2(k0.x, k0.y);
            ku.y = pack2(k0.z, k0.w);
            ku.z = pack2(k1.x, k1.y);
            ku.w = pack2(k1.z, k1.w);
            *(uint4*)(smem + kKOff + row * 64 + col) = ku;
            float4 v0 = *(const float4*)(smem + kSVOff + row * 128 + oc * 8);
            float4 v1 = *(const float4*)(smem + kSVOff + row * 128 + oc * 8 + 4);
            uint4 vu;
            vu.x = pack2(v0.x, v0.y);
            vu.y = pack2(v0.z, v0.w);
            vu.z = pack2(v1.x, v1.y);
            vu.w = pack2(v1.z, v1.w);
            *(uint4*)(smem + kVOff + row * 64 + col) = vu;
        }
    };

    // ---- prologue A: ctx slots -> smem; Q -> smem (K+V tile region) ----
    for (int i = tid; i < kCtxOld; i += kThreads) {
        const size_t ci = (size_t)s * kKvLen + i;
        smem[kCtxOff + i] =
            (uint32_t)(ctx_is64 ? ctx32[2 * ci] : ctx32[ci]);
    }
    {
        const int r = tid >> 1;   // 0..127
        const int hh = tid & 1;
        const float* src =
            q + ((size_t)(s * kQLen + q0 + r) * kHeads + h) * kHeadDim + hh * 64;
        uint32_t* dst = smem + kKOff + r * 64 + hh * 32;  // K+V region (8192)
#pragma unroll
        for (int i = 0; i < 16; i++) {
            float4 f = *(const float4*)(src + i * 4);
            uint2 u;
            u.x = pack2(f.x * kScaleLog2e, f.y * kScaleLog2e);
            u.y = pack2(f.z * kScaleLog2e, f.w * kScaleLog2e);
            *(uint2*)(dst + 2 * i) = u;
        }
    }
    __syncthreads();  // ctx visible (gather reads it); Q visible

    // ---- prologue B: start tile-0 gather, load Q frags, convert tile 0 ----
    issue_gather(0);

    const int qr0 = warp * 16;
    uint32_t qf[8][4];
#pragma unroll
    for (int ks = 0; ks < 8; ks++) {
        const uint32_t* r0 = smem + kKOff + (qr0 + g) * 64 + ks * 8;
        qf[ks][0] = r0[t];
        qf[ks][1] = r0[8 * 64 + t];
        qf[ks][2] = r0[t + 4];
        qf[ks][3] = r0[8 * 64 + t + 4];
    }
    CP_WAIT0();
    __syncthreads();  // qf reads done; staging full
    convert_tiles();
    __syncthreads();

    float oacc[16][4];
#pragma unroll
    for (int nb = 0; nb < 16; nb++)
        oacc[nb][0] = oacc[nb][1] = oacc[nb][2] = oacc[nb][3] = 0.f;
    float m1 = -CUDART_INF_F, m2 = -CUDART_INF_F;
    float l1 = 0.f, l2 = 0.f;

    const int m_id = lane >> 3;   // ldmatrix matrix index within x4
    const int lr   = lane & 7;    // row within matrix

    for (int tile = 0; tile < n_tiles; tile++) {
        const int j0 = tile * BN;

        // prefetch next tile into staging while computing this one
        if (tile + 1 < n_tiles) issue_gather(j0 + BN);

        // ---- S = Q K^T  (b-frags via ldmatrix.x4, 2 nb per instr) ----
        float sacc[8][4];
#pragma unroll
        for (int nb = 0; nb < 8; nb++)
            sacc[nb][0] = sacc[nb][1] = sacc[nb][2] = sacc[nb][3] = 0.f;

#pragma unroll
        for (int ks = 0; ks < 8; ks++) {
#pragma unroll
            for (int nbp = 0; nbp < 4; nbp++) {
                const int row_n = nbp * 16 + (m_id >> 1) * 8 + lr;
                const uint32_t addr =
                    sb + (uint32_t)(kKOff + row_n * 64 +
                                    (((ks * 2 + (m_id & 1)) ^ (row_n & 7)) << 2)) * 4;
                uint32_t b4[4];
                ldm_x4(b4, addr);
                mma_f16(sacc[2 * nbp], qf[ks], b4);
                mma_f16(sacc[2 * nbp + 1], qf[ks], b4 + 2);
            }
        }

        // ---- bottom-right causal mask (boundary tiles only) ----
        if (j0 + BN - 1 > q0 + kCtxOld) {
            const int lim1 = q0 + qr0 + g + kCtxOld;
            const int lim2 = lim1 + 8;
#pragma unroll
            for (int nb = 0; nb < 8; nb++) {
                const int c0 = j0 + nb * 8 + 2 * t;
                const int c1 = c0 + 1;
                if (c0 > lim1) sacc[nb][0] = -1e30f;
                if (c1 > lim1) sacc[nb][1] = -1e30f;
                if (c0 > lim2) sacc[nb][2] = -1e30f;
                if (c1 > lim2) sacc[nb][3] = -1e30f;
            }
        }

        // ---- online softmax (exp2 domain); tree max; P -> A-frags ----
        float t1[4], t2[4];
#pragma unroll
        for (int i = 0; i < 4; i++) {
            t1[i] = fmaxf(fmaxf(sacc[2 * i][0], sacc[2 * i][1]),
                          fmaxf(sacc[2 * i + 1][0], sacc[2 * i + 1][1]));
            t2[i] = fmaxf(fmaxf(sacc[2 * i][2], sacc[2 * i][3]),
                          fmaxf(sacc[2 * i + 1][2], sacc[2 * i + 1][3]));
        }
        float mx1 = fmaxf(fmaxf(t1[0], t1[1]), fmaxf(t1[2], t1[3]));
        float mx2 = fmaxf(fmaxf(t2[0], t2[1]), fmaxf(t2[2], t2[3]));
        mx1 = fmaxf(mx1, __shfl_xor_sync(0xffffffffu, mx1, 1));
        mx1 = fmaxf(mx1, __shfl_xor_sync(0xffffffffu, mx1, 2));
        mx2 = fmaxf(mx2, __shfl_xor_sync(0xffffffffu, mx2, 1));
        mx2 = fmaxf(mx2, __shfl_xor_sync(0xffffffffu, mx2, 2));

        const float m1n = fmaxf(m1, mx1);
        const float m2n = fmaxf(m2, mx2);
        const float al1 = fast_exp2(m1 - m1n);
        const float al2 = fast_exp2(m2 - m2n);
        m1 = m1n;
        m2 = m2n;

        // pa[nb] = fp16x2 P(rows g),  pb[nb] = fp16x2 P(rows g+8).
        // For PV kstep ks: a = {pa[2ks], pb[2ks], pa[2ks+1], pb[2ks+1]}
        // (accumulator layout == m16n8k16 A-operand layout, packed).
        uint32_t pa[8], pb[8];
        float sum1 = 0.f, sum2 = 0.f;
#pragma unroll
        for (int nb = 0; nb < 8; nb++) {
            const float p0 = fast_exp2(sacc[nb][0] - m1);
            const float p1 = fast_exp2(sacc[nb][1] - m1);
            const float p2 = fast_exp2(sacc[nb][2] - m2);
            const float p3 = fast_exp2(sacc[nb][3] - m2);
            sum1 += p0 + p1;
            sum2 += p2 + p3;
            pa[nb] = pack2(p0, p1);
            pb[nb] = pack2(p2, p3);
        }
        sum1 += __shfl_xor_sync(0xffffffffu, sum1, 1);
        sum1 += __shfl_xor_sync(0xffffffffu, sum1, 2);
        sum2 += __shfl_xor_sync(0xffffffffu, sum2, 1);
        sum2 += __shfl_xor_sync(0xffffffffu, sum2, 2);
        l1 = l1 * al1 + sum1;
        l2 = l2 * al2 + sum2;

        // warp-voted rescale skip: al == 1.0 exactly when max unchanged
        if (__any_sync(0xffffffffu, (al1 < 1.f) || (al2 < 1.f))) {
#pragma unroll
            for (int nb = 0; nb < 16; nb++) {
                oacc[nb][0] *= al1;
                oacc[nb][1] *= al1;
                oacc[nb][2] *= al2;
                oacc[nb][3] *= al2;
            }
        }

        // ---- O += P V  (a from registers, b via ldmatrix.trans) ----
#pragma unroll
        for (int ks = 0; ks < 4; ks++) {
            const uint32_t a[4] = {pa[2 * ks], pb[2 * ks],
                                   pa[2 * ks + 1], pb[2 * ks + 1]};
#pragma unroll
            for (int nbp = 0; nbp < 8; nbp++) {
                const int row_j = ks * 16 + (m_id & 1) * 8 + lr;
                const uint32_t addr =
                    sb + (uint32_t)(kVOff + row_j * 64 +
                                    (((nbp * 2 + (m_id >> 1)) ^ (row_j & 7)) << 2)) * 4;
                uint32_t b4[4];
                ldm_x4_t(b4, addr);
                mma_f16(oacc[2 * nbp], a, b4);
                mma_f16(oacc[2 * nbp + 1], a, b4 + 2);
            }
        }

        // ---- swap in the prefetched tile ----
        if (tile + 1 < n_tiles) {
            CP_WAIT0();
            __syncthreads();   // tile reads done; staging complete
            convert_tiles();
            __syncthreads();
        }
    }

    // ---- epilogue: normalize and store ----
    const float inv1 = 1.f / l1;
    const float inv2 = 1.f / l2;
    const int row1 = s * kQLen + q0 + qr0 + g;
    float* o1 = out + (size_t)row1 * kOutCols + h * kHeadDim;
    float* o2 = o1 + (size_t)8 * kOutCols;
#pragma unroll
    for (int nb = 0; nb < 16; nb++) {
        const int cc = nb * 8 + 2 * t;
        float2 w1 = make_float2(oacc[nb][0] * inv1, oacc[nb][1] * inv1);
        float2 w2 = make_float2(oacc[nb][2] * inv2, oacc[nb][3] * inv2);
        *(float2*)(o1 + cc) = w1;
        *(float2*)(o2 + cc) = w2;
    }
}

extern "C" void kernel_launch(void* const* d_in, const int* in_sizes, int n_in,
                              void* d_out, int out_size) {
    const float* q  = (const float*)d_in[0];
    const float* k  = (const float*)d_in[1];
    const float* v  = (const float*)d_in[2];
    const float* kc = (const float*)d_in[3];
    const float* vc = (const float*)d_in[4];
    const int* ctx = (const int*)d_in[6];
    float* out = (float*)d_out;

    const int smem_bytes = kSmemU32 * (int)sizeof(uint32_t);
    cudaFuncSetAttribute(fa_fp16_kernel,
                         cudaFuncAttributeMaxDynamicSharedMemorySize, smem_bytes);
    dim3 grid(kQLen / BM, kHeads, kNSeqs);
    fa_fp16_kernel<<<grid, kThreads, smem_bytes>>>(q, k, v, kc, vc, ctx, out);
}

// round 16
// speedup vs baseline: 1.1496x; 1.1496x over previous
#include <cuda_runtime.h>
#include <cuda_fp16.h>
#include <cstdint>
#include <math_constants.h>

// ---------------------------------------------------------------------------
// Paged-cache block-diagonal causal attention (fill chunk), fused flash-attn.
// FP16 mma.sync m16n8k16 (fp32 accum), fp32 I/O.
// R16: exact R14 structure + deferred l-reduction (lane-partial l, single
// epilogue reduce) + tree max. cp.async staging pipeline, ctx smem prefetch,
// BM=128, direct S-accumulator -> PV A-fragment packing.
//
// kv j < 1792 -> cache[ctx32[s*2048+j]];  j >= 1792 -> new k/v row j-1792.
// Mask: kv j visible to query i iff j <= i + 1792.
// ---------------------------------------------------------------------------

namespace {
constexpr int kNSeqs   = 8;
constexpr int kQLen    = 256;
constexpr int kKvLen   = 2048;
constexpr int kHeads   = 16;
constexpr int kHeadDim = 128;
constexpr int kCtxOld  = 1792;
constexpr int kOutCols = 2048;

constexpr int BM = 128;
constexpr int BN = 64;
constexpr int kThreads = 256;  // 8 warps, 16 query rows each

constexpr float kScaleLog2e = 0.08838834764831845f * 1.4426950408889634f;

// u32 offsets. fp16 K/V tiles: 64 rows x 64 u32, XOR-swizzled
// (16B chunk index ^ (row & 7)). ctx slots: 1792 ints.
// fp32 staging: K,V 64 rows x 128 u32 each.
// Q prologue (128 rows x 64 u32) aliases the K+V tile regions exactly.
constexpr int kKOff   = 0;
constexpr int kVOff   = 4096;
constexpr int kCtxOff = 8192;
constexpr int kSKOff  = kCtxOff + kCtxOld;     // 9984
constexpr int kSVOff  = kSKOff + 64 * 128;     // 18176
constexpr int kSmemU32 = kSVOff + 64 * 128;    // 26368 u32 = 105472 B
}  // namespace

__device__ __forceinline__ uint32_t smem_u32(const void* p) {
    uint32_t a;
    asm("{ .reg .u64 t; cvta.to.shared.u64 t, %1; cvt.u32.u64 %0, t; }"
        : "=r"(a) : "l"(p));
    return a;
}

__device__ __forceinline__ uint32_t pack2(float lo, float hi) {
    __half2 h = __floats2half2_rn(lo, hi);
    return *reinterpret_cast<uint32_t*>(&h);
}

__device__ __forceinline__ float fast_exp2(float x) {
    float r;
    asm("ex2.approx.ftz.f32 %0, %1;" : "=f"(r) : "f"(x));
    return r;
}

__device__ __forceinline__ void mma_f16(float c[4], const uint32_t a[4],
                                        const uint32_t* b) {
    asm volatile(
        "mma.sync.aligned.m16n8k16.row.col.f32.f16.f16.f32 "
        "{%0,%1,%2,%3}, {%4,%5,%6,%7}, {%8,%9}, {%0,%1,%2,%3};"
        : "+f"(c[0]), "+f"(c[1]), "+f"(c[2]), "+f"(c[3])
        : "r"(a[0]), "r"(a[1]), "r"(a[2]), "r"(a[3]), "r"(b[0]), "r"(b[1]));
}

__device__ __forceinline__ void ldm_x4(uint32_t r[4], uint32_t addr) {
    asm volatile(
        "ldmatrix.sync.aligned.m8n8.x4.shared.b16 {%0,%1,%2,%3}, [%4];"
        : "=r"(r[0]), "=r"(r[1]), "=r"(r[2]), "=r"(r[3]) : "r"(addr));
}

__device__ __forceinline__ void ldm_x4_t(uint32_t r[4], uint32_t addr) {
    asm volatile(
        "ldmatrix.sync.aligned.m8n8.x4.trans.shared.b16 {%0,%1,%2,%3}, [%4];"
        : "=r"(r[0]), "=r"(r[1]), "=r"(r[2]), "=r"(r[3]) : "r"(addr));
}

#define CP_ASYNC16(dst, src) \
    asm volatile("cp.async.cg.shared.global [%0], [%1], 16;" \
                 :: "r"(dst), "l"(src) : "memory")
#define CP_COMMIT() asm volatile("cp.async.commit_group;" ::: "memory")
#define CP_WAIT0()  asm volatile("cp.async.wait_group 0;" ::: "memory")

__global__ void __launch_bounds__(kThreads, 1)
fa_fp16_kernel(const float* __restrict__ q, const float* __restrict__ kk,
               const float* __restrict__ vv, const float* __restrict__ k_cache,
               const float* __restrict__ v_cache,
               const int* __restrict__ ctx32, float* __restrict__ out) {
    extern __shared__ uint32_t smem[];
    const uint32_t sb = smem_u32(smem);

    const int qt = blockIdx.x;   // 0..1
    const int h  = blockIdx.y;   // 0..15
    const int s  = blockIdx.z;   // 0..7
    const int q0 = qt * BM;

    const int tid  = threadIdx.x;
    const int warp = tid >> 5;
    const int lane = tid & 31;
    const int g = lane >> 2;
    const int t = lane & 3;

    // ctx dtype probe (int64 LE -> odd words 1,3,5 all zero)
    const bool ctx_is64 =
        (ctx32[1] == 0) && (ctx32[3] == 0) && (ctx32[5] == 0);

    const int n_tiles = (q0 + BM - 1 + kCtxOld + 1 + BN - 1) / BN;  // 30 or 32

    const int rseg = lane >> 3;  // gather: row within group of 4
    const int c    = lane & 7;   // gather: 16B fp32 chunk within 128B pass

    // ---- issue cp.async gather of one tile into fp32 staging ----
    auto issue_gather = [&](int j0) {
#pragma unroll
        for (int rg = 0; rg < 2; rg++) {
            const int row = warp * 8 + rg * 4 + rseg;
            const int j = j0 + row;
            const float *ksrc, *vsrc;
            if (j < kCtxOld) {
                const int slot = (int)smem[kCtxOff + j];
                const size_t base = ((size_t)slot * kHeads + h) * kHeadDim;
                ksrc = k_cache + base;
                vsrc = v_cache + base;
            } else {
                const size_t base =
                    ((size_t)(s * kQLen + (j - kCtxOld)) * kHeads + h) * kHeadDim;
                ksrc = kk + base;
                vsrc = vv + base;
            }
#pragma unroll
            for (int pass = 0; pass < 4; pass++) {
                const uint32_t off =
                    (uint32_t)(row * 128 + pass * 32 + c * 4) * 4;
                CP_ASYNC16(sb + (uint32_t)kSKOff * 4 + off,
                           ksrc + pass * 32 + c * 4);
                CP_ASYNC16(sb + (uint32_t)kSVOff * 4 + off,
                           vsrc + pass * 32 + c * 4);
            }
        }
        CP_COMMIT();
    };

    // ---- convert fp32 staging -> swizzled fp16 tiles (R14 layout) ----
    auto convert_tiles = [&]() {
#pragma unroll
        for (int it = 0; it < 8; it++) {
            const int chunk = tid + it * 256;   // 2048 chunks per tensor
            const int row = chunk >> 5;
            const int cc  = chunk & 31;
            const int col = (((cc >> 1) ^ (row & 7)) << 2) + (cc & 1) * 2;
            float4 kf = *(const float4*)(smem + kSKOff + chunk * 4);
            uint2 ku;
            ku.x = pack2(kf.x, kf.y);
            ku.y = pack2(kf.z, kf.w);
            *(uint2*)(smem + kKOff + row * 64 + col) = ku;
            float4 vf = *(const float4*)(smem + kSVOff + chunk * 4);
            uint2 vu;
            vu.x = pack2(vf.x, vf.y);
            vu.y = pack2(vf.z, vf.w);
            *(uint2*)(smem + kVOff + row * 64 + col) = vu;
        }
    };

    // ---- prologue A: ctx slots -> smem; Q -> smem (K+V tile region) ----
    for (int i = tid; i < kCtxOld; i += kThreads) {
        const size_t ci = (size_t)s * kKvLen + i;
        smem[kCtxOff + i] =
            (uint32_t)(ctx_is64 ? ctx32[2 * ci] : ctx32[ci]);
    }
    {
        const int r = tid >> 1;   // 0..127
        const int hh = tid & 1;
        const float* src =
            q + ((size_t)(s * kQLen + q0 + r) * kHeads + h) * kHeadDim + hh * 64;
        uint32_t* dst = smem + kKOff + r * 64 + hh * 32;  // K+V region (8192)
#pragma unroll
        for (int i = 0; i < 16; i++) {
            float4 f = *(const float4*)(src + i * 4);
            uint2 u;
            u.x = pack2(f.x * kScaleLog2e, f.y * kScaleLog2e);
            u.y = pack2(f.z * kScaleLog2e, f.w * kScaleLog2e);
            *(uint2*)(dst + 2 * i) = u;
        }
    }
    __syncthreads();  // ctx visible (gather reads it); Q visible

    // ---- prologue B: start tile-0 gather, load Q frags, convert tile 0 ----
    issue_gather(0);

    const int qr0 = warp * 16;
    uint32_t qf[8][4];
#pragma unroll
    for (int ks = 0; ks < 8; ks++) {
        const uint32_t* r0 = smem + kKOff + (qr0 + g) * 64 + ks * 8;
        qf[ks][0] = r0[t];
        qf[ks][1] = r0[8 * 64 + t];
        qf[ks][2] = r0[t + 4];
        qf[ks][3] = r0[8 * 64 + t + 4];
    }
    CP_WAIT0();
    __syncthreads();  // qf reads done; staging full
    convert_tiles();
    __syncthreads();

    float oacc[16][4];
#pragma unroll
    for (int nb = 0; nb < 16; nb++)
        oacc[nb][0] = oacc[nb][1] = oacc[nb][2] = oacc[nb][3] = 0.f;
    float m1 = -CUDART_INF_F, m2 = -CUDART_INF_F;
    float l1 = 0.f, l2 = 0.f;   // LANE-PARTIAL sums; reduced in epilogue

    const int m_id = lane >> 3;   // ldmatrix matrix index within x4
    const int lr   = lane & 7;    // row within matrix

    for (int tile = 0; tile < n_tiles; tile++) {
        const int j0 = tile * BN;

        // prefetch next tile into staging while computing this one
        if (tile + 1 < n_tiles) issue_gather(j0 + BN);

        // ---- S = Q K^T  (b-frags via ldmatrix.x4, 2 nb per instr) ----
        float sacc[8][4];
#pragma unroll
        for (int nb = 0; nb < 8; nb++)
            sacc[nb][0] = sacc[nb][1] = sacc[nb][2] = sacc[nb][3] = 0.f;

#pragma unroll
        for (int ks = 0; ks < 8; ks++) {
#pragma unroll
            for (int nbp = 0; nbp < 4; nbp++) {
                const int row_n = nbp * 16 + (m_id >> 1) * 8 + lr;
                const uint32_t addr =
                    sb + (uint32_t)(kKOff + row_n * 64 +
                                    (((ks * 2 + (m_id & 1)) ^ (row_n & 7)) << 2)) * 4;
                uint32_t b4[4];
                ldm_x4(b4, addr);
                mma_f16(sacc[2 * nbp], qf[ks], b4);
                mma_f16(sacc[2 * nbp + 1], qf[ks], b4 + 2);
            }
        }

        // ---- bottom-right causal mask (boundary tiles only) ----
        if (j0 + BN - 1 > q0 + kCtxOld) {
            const int lim1 = q0 + qr0 + g + kCtxOld;
            const int lim2 = lim1 + 8;
#pragma unroll
            for (int nb = 0; nb < 8; nb++) {
                const int c0 = j0 + nb * 8 + 2 * t;
                const int c1 = c0 + 1;
                if (c0 > lim1) sacc[nb][0] = -1e30f;
                if (c1 > lim1) sacc[nb][1] = -1e30f;
                if (c0 > lim2) sacc[nb][2] = -1e30f;
                if (c1 > lim2) sacc[nb][3] = -1e30f;
            }
        }

        // ---- online softmax (exp2 domain); tree max; P -> A-frags ----
        float t1[4], t2[4];
#pragma unroll
        for (int i = 0; i < 4; i++) {
            t1[i] = fmaxf(fmaxf(sacc[2 * i][0], sacc[2 * i][1]),
                          fmaxf(sacc[2 * i + 1][0], sacc[2 * i + 1][1]));
            t2[i] = fmaxf(fmaxf(sacc[2 * i][2], sacc[2 * i][3]),
                          fmaxf(sacc[2 * i + 1][2], sacc[2 * i + 1][3]));
        }
        float mx1 = fmaxf(fmaxf(t1[0], t1[1]), fmaxf(t1[2], t1[3]));
        float mx2 = fmaxf(fmaxf(t2[0], t2[1]), fmaxf(t2[2], t2[3]));
        mx1 = fmaxf(mx1, __shfl_xor_sync(0xffffffffu, mx1, 1));
        mx1 = fmaxf(mx1, __shfl_xor_sync(0xffffffffu, mx1, 2));
        mx2 = fmaxf(mx2, __shfl_xor_sync(0xffffffffu, mx2, 1));
        mx2 = fmaxf(mx2, __shfl_xor_sync(0xffffffffu, mx2, 2));

        const float m1n = fmaxf(m1, mx1);
        const float m2n = fmaxf(m2, mx2);
        const float al1 = fast_exp2(m1 - m1n);
        const float al2 = fast_exp2(m2 - m2n);
        m1 = m1n;
        m2 = m2n;

        // pa[nb] = fp16x2 P(rows g),  pb[nb] = fp16x2 P(rows g+8).
        // For PV kstep ks: a = {pa[2ks], pb[2ks], pa[2ks+1], pb[2ks+1]}
        // (accumulator layout == m16n8k16 A-operand layout, packed).
        uint32_t pa[8], pb[8];
        float sum1 = 0.f, sum2 = 0.f;
#pragma unroll
        for (int nb = 0; nb < 8; nb++) {
            const float p0 = fast_exp2(sacc[nb][0] - m1);
            const float p1 = fast_exp2(sacc[nb][1] - m1);
            const float p2 = fast_exp2(sacc[nb][2] - m2);
            const float p3 = fast_exp2(sacc[nb][3] - m2);
            sum1 += p0 + p1;
            sum2 += p2 + p3;
            pa[nb] = pack2(p0, p1);
            pb[nb] = pack2(p2, p3);
        }
        // deferred reduction: keep l lane-partial (al is quad-uniform, update
        // is linear, so cross-lane reduce commutes to the epilogue)
        l1 = l1 * al1 + sum1;
        l2 = l2 * al2 + sum2;

#pragma unroll
        for (int nb = 0; nb < 16; nb++) {
            oacc[nb][0] *= al1;
            oacc[nb][1] *= al1;
            oacc[nb][2] *= al2;
            oacc[nb][3] *= al2;
        }

        // ---- O += P V  (a from registers, b via ldmatrix.trans) ----
#pragma unroll
        for (int ks = 0; ks < 4; ks++) {
            const uint32_t a[4] = {pa[2 * ks], pb[2 * ks],
                                   pa[2 * ks + 1], pb[2 * ks + 1]};
#pragma unroll
            for (int nbp = 0; nbp < 8; nbp++) {
                const int row_j = ks * 16 + (m_id & 1) * 8 + lr;
                const uint32_t addr =
                    sb + (uint32_t)(kVOff + row_j * 64 +
                                    (((nbp * 2 + (m_id >> 1)) ^ (row_j & 7)) << 2)) * 4;
                uint32_t b4[4];
                ldm_x4_t(b4, addr);
                mma_f16(oacc[2 * nbp], a, b4);
                mma_f16(oacc[2 * nbp + 1], a, b4 + 2);
            }
        }

        // ---- swap in the prefetched tile ----
        if (tile + 1 < n_tiles) {
            CP_WAIT0();
            __syncthreads();   // tile reads done; staging complete
            convert_tiles();
            __syncthreads();
        }
    }

    // ---- epilogue: reduce lane-partial l across quads, normalize, store ----
    l1 += __shfl_xor_sync(0xffffffffu, l1, 1);
    l1 += __shfl_xor_sync(0xffffffffu, l1, 2);
    l2 += __shfl_xor_sync(0xffffffffu, l2, 1);
    l2 += __shfl_xor_sync(0xffffffffu, l2, 2);
    const float inv1 = 1.f / l1;
    const float inv2 = 1.f / l2;
    const int row1 = s * kQLen + q0 + qr0 + g;
    float* o1 = out + (size_t)row1 * kOutCols + h * kHeadDim;
    float* o2 = o1 + (size_t)8 * kOutCols;
#pragma unroll
    for (int nb = 0; nb < 16; nb++) {
        const int cc = nb * 8 + 2 * t;
        float2 w1 = make_float2(oacc[nb][0] * inv1, oacc[nb][1] * inv1);
        float2 w2 = make_float2(oacc[nb][2] * inv2, oacc[nb][3] * inv2);
        *(float2*)(o1 + cc) = w1;
        *(float2*)(o2 + cc) = w2;
    }
}

extern "C" void kernel_launch(void* const* d_in, const int* in_sizes, int n_in,
                              void* d_out, int out_size) {
    const float* q  = (const float*)d_in[0];
    const float* k  = (const float*)d_in[1];
    const float* v  = (const float*)d_in[2];
    const float* kc = (const float*)d_in[3];
    const float* vc = (const float*)d_in[4];
    const int* ctx = (const int*)d_in[6];
    float* out = (float*)d_out;

    const int smem_bytes = kSmemU32 * (int)sizeof(uint32_t);
    cudaFuncSetAttribute(fa_fp16_kernel,
                         cudaFuncAttributeMaxDynamicSharedMemorySize, smem_bytes);
    dim3 grid(kQLen / BM, kHeads, kNSeqs);
    fa_fp16_kernel<<<grid, kThreads, smem_bytes>>>(q, k, v, kc, vc, ctx, out);
}